// round 5
// baseline (speedup 1.0000x reference)
#include <cuda_runtime.h>
#include <math.h>
#include <stdint.h>

#define TOKENS 4096
#define HID    4096
#define NEXP   4
#define FDIM   8192
#define OUTD   1792

// ---------------- scratch (device globals; no allocs allowed) ----------------
__device__ __align__(256) float g_H[(size_t)2 * TOKENS * FDIM];   // 256 MB
__device__ __align__(256) float g_Y[(size_t)2 * TOKENS * OUTD];   // 56 MB
__device__ __align__(256) float g_gates[2 * TOKENS];
__device__ __align__(256) int   g_rows[NEXP * TOKENS];
__device__ __align__(256) int   g_cnt[NEXP];

// ---------------- helpers ----------------
__device__ __forceinline__ unsigned f2tf(float x) {
    unsigned r;
    asm("cvt.rna.tf32.f32 %0, %1;" : "=r"(r) : "f"(x));
    return r;
}
__device__ __forceinline__ float4 cvt4(float4 v) {
    float4 o;
    o.x = __uint_as_float(f2tf(v.x));
    o.y = __uint_as_float(f2tf(v.y));
    o.z = __uint_as_float(f2tf(v.z));
    o.w = __uint_as_float(f2tf(v.w));
    return o;
}
__device__ __forceinline__ void mma_tf32(float c[4],
                                         unsigned a0, unsigned a1, unsigned a2, unsigned a3,
                                         unsigned b0, unsigned b1) {
    asm volatile(
        "mma.sync.aligned.m16n8k8.row.col.f32.tf32.tf32.f32 "
        "{%0,%1,%2,%3}, {%4,%5,%6,%7}, {%8,%9}, {%0,%1,%2,%3};\n"
        : "+f"(c[0]), "+f"(c[1]), "+f"(c[2]), "+f"(c[3])
        : "r"(a0), "r"(a1), "r"(a2), "r"(a3), "r"(b0), "r"(b1));
}
__device__ __forceinline__ float gelu_exact(float x) {
    return 0.5f * x * (1.0f + erff(x * 0.70710678118654752440f));
}

// ---------------- init ----------------
__global__ void init_cnt_kernel(int* cnt) {
    if (threadIdx.x < NEXP) cnt[threadIdx.x] = 0;
}

// ---------------- router: 1 warp per token ----------------
__global__ void __launch_bounds__(256) router_kernel(
    const float* __restrict__ hs, const float* __restrict__ rw,
    const float* __restrict__ rb, int* __restrict__ cnt,
    int* __restrict__ rows, float* __restrict__ gates) {
    int warp = threadIdx.x >> 5;
    int lane = threadIdx.x & 31;
    int t = blockIdx.x * 8 + warp;
    if (t >= TOKENS) return;

    float a0 = 0.f, a1 = 0.f, a2 = 0.f, a3 = 0.f;
    const float4* x = (const float4*)(hs + (size_t)t * HID);
    const float4* w = (const float4*)rw;
    #pragma unroll 4
    for (int i = lane; i < HID / 4; i += 32) {
        float4 v = x[i];
        float4 w0 = w[4 * i + 0];
        float4 w1 = w[4 * i + 1];
        float4 w2 = w[4 * i + 2];
        float4 w3 = w[4 * i + 3];
        a0 += v.x * w0.x + v.y * w1.x + v.z * w2.x + v.w * w3.x;
        a1 += v.x * w0.y + v.y * w1.y + v.z * w2.y + v.w * w3.y;
        a2 += v.x * w0.z + v.y * w1.z + v.z * w2.z + v.w * w3.z;
        a3 += v.x * w0.w + v.y * w1.w + v.z * w2.w + v.w * w3.w;
    }
    #pragma unroll
    for (int s = 16; s > 0; s >>= 1) {
        a0 += __shfl_xor_sync(0xffffffffu, a0, s);
        a1 += __shfl_xor_sync(0xffffffffu, a1, s);
        a2 += __shfl_xor_sync(0xffffffffu, a2, s);
        a3 += __shfl_xor_sync(0xffffffffu, a3, s);
    }
    if (lane == 0) {
        float l[NEXP] = {a0 + rb[0], a1 + rb[1], a2 + rb[2], a3 + rb[3]};
        int i0 = 0;
        #pragma unroll
        for (int e = 1; e < NEXP; e++)
            if (l[e] > l[i0]) i0 = e;
        int i1 = -1;
        #pragma unroll
        for (int e = 0; e < NEXP; e++) {
            if (e == i0) continue;
            if (i1 < 0 || l[e] > l[i1]) i1 = e;
        }
        float q = expf(l[i1] - l[i0]);  // <= 1
        float g0 = 1.0f / (1.0f + q);
        float g1 = q / (1.0f + q);
        int p0 = atomicAdd(&cnt[i0], 1);
        rows[i0 * TOKENS + p0] = 2 * t;
        int p1 = atomicAdd(&cnt[i1], 1);
        rows[i1 * TOKENS + p1] = 2 * t + 1;
        gates[2 * t] = g0;
        gates[2 * t + 1] = g1;
    }
}

// ---------------- expert GEMM (tf32 mma.sync), 512 threads ----------------
// CTA tile 128x256, BK=16, 16 warps (4x4), warp tile 32x64.
#define BM 128
#define BN 256
#define BKK 16
#define ASTR 20   // BKK + 4 pad
#define BSTR 264  // BN + 8 pad
#define SMEM_BYTES (size_t)(2 * (BM * ASTR + BKK * BSTR) * 4)
#define NTHR 512

template <bool GATHER_SHIFT, bool DO_GELU>
__global__ void __launch_bounds__(NTHR, 1) gemm_moe_kernel(
    const float* __restrict__ Abase, const float* __restrict__ W,
    const float* __restrict__ bias, float* __restrict__ Out,
    const int* __restrict__ rows_list, const int* __restrict__ cnt,
    int N, int K) {
    const int e = blockIdx.z;
    const int m0 = blockIdx.y * BM;
    const int n0 = blockIdx.x * BN;
    const int cn = cnt[e];
    if (m0 >= cn) return;

    extern __shared__ float sm[];
    float* As = sm;                      // [2][BM][ASTR]
    float* Bs = sm + 2 * BM * ASTR;      // [2][BKK][BSTR]
    const int ASZ = BM * ASTR;
    const int BSZ = BKK * BSTR;

    const int tid = threadIdx.x;
    const int lane = tid & 31;
    const int warp = tid >> 5;
    const int g = lane >> 2;
    const int t = lane & 3;
    const int wm = warp >> 2;  // 0..3 -> m offset 32*wm
    const int wn = warp & 3;   // 0..3 -> n offset 64*wn

    const float* Wp = W + (size_t)e * K * N + n0;

    // A staging: 1 float4 per thread (512 * 4 = 128*16)
    const int arow = tid >> 2;
    const int aq = tid & 3;
    int gr0 = rows_list[e * TOKENS + m0 + arow];
    size_t aoff = (size_t)(GATHER_SHIFT ? (gr0 >> 1) : gr0) * K + aq * 4;

    // B staging: 2 float4 per thread (1024 * 4 = 16*256)
    int bk[2], bnq[2];
    #pragma unroll
    for (int n = 0; n < 2; n++) {
        int L = tid + n * NTHR;
        bk[n] = L >> 6;
        bnq[n] = L & 63;
    }

    float c[2][8][4];
    #pragma unroll
    for (int mi = 0; mi < 2; mi++)
        #pragma unroll
        for (int ni = 0; ni < 8; ni++)
            #pragma unroll
            for (int r = 0; r < 4; r++) c[mi][ni][r] = 0.f;

    const int KT = K / BKK;
    float4 ra, rb[2];

    // prologue: tile 0
    ra = *(const float4*)(Abase + aoff);
    #pragma unroll
    for (int n = 0; n < 2; n++)
        rb[n] = *(const float4*)(Wp + (size_t)bk[n] * N + bnq[n] * 4);
    *(float4*)&As[arow * ASTR + aq * 4] = cvt4(ra);
    #pragma unroll
    for (int n = 0; n < 2; n++)
        *(float4*)&Bs[bk[n] * BSTR + bnq[n] * 4] = cvt4(rb[n]);
    __syncthreads();

    for (int kt = 0; kt < KT; kt++) {
        if (kt + 1 < KT) {
            int kbase = (kt + 1) * BKK;
            ra = *(const float4*)(Abase + aoff + kbase);
            #pragma unroll
            for (int n = 0; n < 2; n++)
                rb[n] = *(const float4*)(Wp + (size_t)(kbase + bk[n]) * N + bnq[n] * 4);
        }
        const float* A_ = As + (kt & 1) * ASZ;
        const float* B_ = Bs + (kt & 1) * BSZ;
        #pragma unroll
        for (int ks = 0; ks < 2; ks++) {
            const int kk = ks * 8;
            unsigned a[2][4];
            #pragma unroll
            for (int mi = 0; mi < 2; mi++) {
                int mb = wm * 32 + mi * 16;
                a[mi][0] = __float_as_uint(A_[(mb + g) * ASTR + kk + t]);
                a[mi][1] = __float_as_uint(A_[(mb + g + 8) * ASTR + kk + t]);
                a[mi][2] = __float_as_uint(A_[(mb + g) * ASTR + kk + t + 4]);
                a[mi][3] = __float_as_uint(A_[(mb + g + 8) * ASTR + kk + t + 4]);
            }
            #pragma unroll
            for (int ni = 0; ni < 8; ni++) {
                int nb = wn * 64 + ni * 8;
                unsigned b0 = __float_as_uint(B_[(kk + t) * BSTR + nb + g]);
                unsigned b1 = __float_as_uint(B_[(kk + t + 4) * BSTR + nb + g]);
                #pragma unroll
                for (int mi = 0; mi < 2; mi++)
                    mma_tf32(c[mi][ni], a[mi][0], a[mi][1], a[mi][2], a[mi][3], b0, b1);
            }
        }
        if (kt + 1 < KT) {
            float* An = As + ((kt + 1) & 1) * ASZ;
            float* Bn = Bs + ((kt + 1) & 1) * BSZ;
            *(float4*)&An[arow * ASTR + aq * 4] = cvt4(ra);
            #pragma unroll
            for (int n = 0; n < 2; n++)
                *(float4*)&Bn[bk[n] * BSTR + bnq[n] * 4] = cvt4(rb[n]);
        }
        __syncthreads();
    }

    // epilogue
    #pragma unroll
    for (int mi = 0; mi < 2; mi++) {
        int r0 = m0 + wm * 32 + mi * 16 + g;
        int r1 = r0 + 8;
        bool v0 = r0 < cn;
        bool v1 = r1 < cn;
        int gr_a = v0 ? rows_list[e * TOKENS + r0] : 0;
        int gr_b = v1 ? rows_list[e * TOKENS + r1] : 0;
        #pragma unroll
        for (int ni = 0; ni < 8; ni++) {
            int col = n0 + wn * 64 + ni * 8 + 2 * t;
            float2 bv = *(const float2*)(bias + (size_t)e * N + col);
            float x0 = c[mi][ni][0] + bv.x;
            float x1 = c[mi][ni][1] + bv.y;
            float x2 = c[mi][ni][2] + bv.x;
            float x3 = c[mi][ni][3] + bv.y;
            if (DO_GELU) {
                x0 = gelu_exact(x0);
                x1 = gelu_exact(x1);
                x2 = gelu_exact(x2);
                x3 = gelu_exact(x3);
            }
            if (v0) *(float2*)(Out + (size_t)gr_a * N + col) = make_float2(x0, x1);
            if (v1) *(float2*)(Out + (size_t)gr_b * N + col) = make_float2(x2, x3);
        }
    }
}

// ---------------- combine: out[t] = g0*Y[2t] + g1*Y[2t+1] ----------------
__global__ void __launch_bounds__(256) combine_kernel(
    const float* __restrict__ Y, const float* __restrict__ gates,
    float* __restrict__ out) {
    int idx = blockIdx.x * blockDim.x + threadIdx.x;
    const int JW = OUTD / 4;  // 448
    if (idx >= TOKENS * JW) return;
    int t = idx / JW;
    int j = idx - t * JW;
    float g0 = gates[2 * t];
    float g1 = gates[2 * t + 1];
    float4 y0 = ((const float4*)(Y + (size_t)(2 * t) * OUTD))[j];
    float4 y1 = ((const float4*)(Y + (size_t)(2 * t + 1) * OUTD))[j];
    float4 o;
    o.x = g0 * y0.x + g1 * y1.x;
    o.y = g0 * y0.y + g1 * y1.y;
    o.z = g0 * y0.z + g1 * y1.z;
    o.w = g0 * y0.w + g1 * y1.w;
    ((float4*)(out + (size_t)t * OUTD))[j] = o;
}

// ---------------- launch ----------------
extern "C" void kernel_launch(void* const* d_in, const int* in_sizes, int n_in,
                              void* d_out, int out_size) {
    const float* hs = (const float*)d_in[0];
    const float* rw = (const float*)d_in[1];
    const float* rb = (const float*)d_in[2];
    const float* w1 = (const float*)d_in[3];
    const float* b1 = (const float*)d_in[4];
    const float* w2 = (const float*)d_in[5];
    const float* b2 = (const float*)d_in[6];
    float* out = (float*)d_out;

    float *H, *Y, *gates;
    int *cnt, *rows;
    cudaGetSymbolAddress((void**)&H, g_H);
    cudaGetSymbolAddress((void**)&Y, g_Y);
    cudaGetSymbolAddress((void**)&gates, g_gates);
    cudaGetSymbolAddress((void**)&cnt, g_cnt);
    cudaGetSymbolAddress((void**)&rows, g_rows);

    cudaFuncSetAttribute((const void*)gemm_moe_kernel<true, true>,
                         cudaFuncAttributeMaxDynamicSharedMemorySize, (int)SMEM_BYTES);
    cudaFuncSetAttribute((const void*)gemm_moe_kernel<false, false>,
                         cudaFuncAttributeMaxDynamicSharedMemorySize, (int)SMEM_BYTES);

    init_cnt_kernel<<<1, 32>>>(cnt);
    router_kernel<<<TOKENS / 8, 256>>>(hs, rw, rb, cnt, rows, gates);

    // GEMM1: hidden (gathered, row=gr>>1) x w1 -> GELU -> H   [N=FDIM, K=HID]
    gemm_moe_kernel<true, true><<<dim3(FDIM / BN, TOKENS / BM, NEXP), NTHR, SMEM_BYTES>>>(
        hs, w1, b1, H, rows, cnt, FDIM, HID);

    // GEMM2: H (row=gr) x w2 -> Y (+b2)   [N=OUTD, K=FDIM]
    gemm_moe_kernel<false, false><<<dim3(OUTD / BN, TOKENS / BM, NEXP), NTHR, SMEM_BYTES>>>(
        H, w2, b2, Y, rows, cnt, OUTD, FDIM);

    combine_kernel<<<(TOKENS * (OUTD / 4) + 255) / 256, 256>>>(Y, gates, out);
}

// round 6
// speedup vs baseline: 1.2899x; 1.2899x over previous
#include <cuda_runtime.h>
#include <cuda_fp16.h>
#include <math.h>
#include <stdint.h>

#define TOKENS 4096
#define HID    4096
#define NEXP   4
#define FDIM   8192
#define OUTD   1792

// GEMM tiling: CTA 128x128, BK=32 (halves), 4 warps @ 64x64, 4-stage cp.async
#define BMM 128
#define BNN 128
#define BKH 32
#define STRH 48                      // halves per smem row (32 + 16 pad) = 96B
#define STAGE_HALVES (2 * BMM * STRH)  // A 6144 + B 6144 = 12288
#define STAGE_BYTES  (STAGE_HALVES * 2)  // 24576
#define NS 4
#define SMEM_DYN (NS * STAGE_BYTES)  // 98304

// ---------------- scratch (device globals) ----------------
__device__ __align__(1024) __half g_A[(size_t)NEXP * TOKENS * HID];    // 128MB
__device__ __align__(1024) __half g_W1P[(size_t)NEXP * FDIM * HID];    // 256MB
__device__ __align__(1024) __half g_W2P[(size_t)NEXP * OUTD * FDIM];   // 112MB
__device__ __align__(1024) __half g_H[(size_t)NEXP * TOKENS * FDIM];   // 256MB
__device__ __align__(1024) float  g_Y[(size_t)2 * TOKENS * OUTD];      // 56MB
__device__ __align__(256) float g_gates[2 * TOKENS];
__device__ __align__(256) int   g_rows[NEXP * TOKENS];
__device__ __align__(256) int   g_cnt[NEXP];

// ---------------- helpers ----------------
__device__ __forceinline__ uint32_t smem_u32(const void* p) {
    uint32_t a;
    asm("{ .reg .u64 t; cvta.to.shared.u64 t, %1; cvt.u32.u64 %0, t; }" : "=r"(a) : "l"(p));
    return a;
}
__device__ __forceinline__ void cpa16(uint32_t dst, const void* src) {
    asm volatile("cp.async.cg.shared.global [%0], [%1], 16;" :: "r"(dst), "l"(src));
}
__device__ __forceinline__ float gelu_exact(float x) {
    return 0.5f * x * (1.0f + erff(x * 0.70710678118654752440f));
}
// k-interleave permutation within 16-groups: order [0,1,8,9,2,3,10,11,4,5,12,13,6,7,14,15]
__device__ __host__ __forceinline__ int pos16(int k) {
    return (k & 1) | (((k >> 1) & 3) << 2) | (((k >> 3) & 1) << 1);
}
__device__ __forceinline__ int inv16(int pos) {
    return (pos & 1) | (((pos >> 2) & 3) << 1) | (((pos >> 1) & 1) << 3);
}

__device__ __forceinline__ void mma_f16(float c[4],
                                        uint32_t a0, uint32_t a1, uint32_t a2, uint32_t a3,
                                        uint32_t b0, uint32_t b1) {
    asm volatile(
        "mma.sync.aligned.m16n8k16.row.col.f32.f16.f16.f32 "
        "{%0,%1,%2,%3}, {%4,%5,%6,%7}, {%8,%9}, {%0,%1,%2,%3};\n"
        : "+f"(c[0]), "+f"(c[1]), "+f"(c[2]), "+f"(c[3])
        : "r"(a0), "r"(a1), "r"(a2), "r"(a3), "r"(b0), "r"(b1));
}

// ---------------- init ----------------
__global__ void init_cnt_kernel(int* cnt) {
    if (threadIdx.x < NEXP) cnt[threadIdx.x] = 0;
}

// ---------------- router: 1 warp per token ----------------
__global__ void __launch_bounds__(256) router_kernel(
    const float* __restrict__ hs, const float* __restrict__ rw,
    const float* __restrict__ rb, int* __restrict__ cnt,
    int* __restrict__ rows, float* __restrict__ gates) {
    int warp = threadIdx.x >> 5;
    int lane = threadIdx.x & 31;
    int t = blockIdx.x * 8 + warp;
    if (t >= TOKENS) return;

    float a0 = 0.f, a1 = 0.f, a2 = 0.f, a3 = 0.f;
    const float4* x = (const float4*)(hs + (size_t)t * HID);
    const float4* w = (const float4*)rw;
    #pragma unroll 4
    for (int i = lane; i < HID / 4; i += 32) {
        float4 v = x[i];
        float4 w0 = w[4 * i + 0];
        float4 w1 = w[4 * i + 1];
        float4 w2 = w[4 * i + 2];
        float4 w3 = w[4 * i + 3];
        a0 += v.x * w0.x + v.y * w1.x + v.z * w2.x + v.w * w3.x;
        a1 += v.x * w0.y + v.y * w1.y + v.z * w2.y + v.w * w3.y;
        a2 += v.x * w0.z + v.y * w1.z + v.z * w2.z + v.w * w3.z;
        a3 += v.x * w0.w + v.y * w1.w + v.z * w2.w + v.w * w3.w;
    }
    #pragma unroll
    for (int s = 16; s > 0; s >>= 1) {
        a0 += __shfl_xor_sync(0xffffffffu, a0, s);
        a1 += __shfl_xor_sync(0xffffffffu, a1, s);
        a2 += __shfl_xor_sync(0xffffffffu, a2, s);
        a3 += __shfl_xor_sync(0xffffffffu, a3, s);
    }
    if (lane == 0) {
        float l[NEXP] = {a0 + rb[0], a1 + rb[1], a2 + rb[2], a3 + rb[3]};
        int i0 = 0;
        #pragma unroll
        for (int e = 1; e < NEXP; e++)
            if (l[e] > l[i0]) i0 = e;
        int i1 = -1;
        #pragma unroll
        for (int e = 0; e < NEXP; e++) {
            if (e == i0) continue;
            if (i1 < 0 || l[e] > l[i1]) i1 = e;
        }
        float q = expf(l[i1] - l[i0]);  // <= 1
        float g0 = 1.0f / (1.0f + q);
        float g1 = q / (1.0f + q);
        int p0 = atomicAdd(&cnt[i0], 1);
        rows[i0 * TOKENS + p0] = 2 * t;
        int p1 = atomicAdd(&cnt[i1], 1);
        rows[i1 * TOKENS + p1] = 2 * t + 1;
        gates[2 * t] = g0;
        gates[2 * t + 1] = g1;
    }
}

// ---------------- gather routed rows -> fp16, k-permuted ----------------
__global__ void __launch_bounds__(128) gather_kernel(
    const float* __restrict__ hs, const int* __restrict__ rows,
    const int* __restrict__ cnt, __half* __restrict__ A) {
    int p = blockIdx.x;
    int e = blockIdx.y;
    if (p >= cnt[e]) return;
    int tok = rows[e * TOKENS + p] >> 1;
    const float4* src = (const float4*)(hs + (size_t)tok * HID);
    __half* dst = A + ((size_t)e * TOKENS + p) * HID;
    // 256 groups of 16; each thread does 2 groups
    for (int gi = threadIdx.x; gi < HID / 16; gi += 128) {
        float f[16];
        #pragma unroll
        for (int q = 0; q < 4; q++) {
            float4 v = src[gi * 4 + q];
            f[q * 4 + 0] = v.x; f[q * 4 + 1] = v.y;
            f[q * 4 + 2] = v.z; f[q * 4 + 3] = v.w;
        }
        __half h[16];
        #pragma unroll
        for (int k = 0; k < 16; k++) h[pos16(k)] = __float2half_rn(f[k]);
        uint4* d = (uint4*)(dst + gi * 16);
        d[0] = ((uint4*)h)[0];
        d[1] = ((uint4*)h)[1];
    }
}

// ---------------- W transpose: [E][K][N] fp32 -> [E][N][Kperm] fp16 ----------------
__global__ void __launch_bounds__(256) wtrans_kernel(
    const float* __restrict__ W, __half* __restrict__ WP, int K, int N) {
    __shared__ float tile[32][33];
    int e = blockIdx.z;
    int n0 = blockIdx.x * 32, k0 = blockIdx.y * 32;
    const float* Wp = W + (size_t)e * K * N;
    __half* Tp = WP + (size_t)e * N * K;
    int tx = threadIdx.x & 31, ty = threadIdx.x >> 5;
    #pragma unroll
    for (int r = ty; r < 32; r += 8)
        tile[r][tx] = Wp[(size_t)(k0 + r) * N + n0 + tx];
    __syncthreads();
    // 256 threads: n = tid>>3 (0..31), s = tid&7 -> 4 output halves each
    int n = threadIdx.x >> 3;
    int s = threadIdx.x & 7;
    __half h[4];
    #pragma unroll
    for (int j = 0; j < 4; j++) {
        int posg = s * 4 + j;
        int k = (posg & 16) | inv16(posg & 15);
        h[j] = __float2half_rn(tile[k][n]);
    }
    *(uint2*)(Tp + (size_t)(n0 + n) * K + k0 + s * 4) = *(uint2*)h;
}

// ---------------- fp16 tensor-core GEMM, cp.async 4-stage ----------------
// A: [E][TOKENS][K] fp16 perm; B: [E][N][K] fp16 perm
// GELU_PERM: out = g_H fp16 perm (GEMM1); else out = g_Y fp32 scattered by rows_list (GEMM2)
template <bool GELU_PERM>
__global__ void __launch_bounds__(128, 2) gemm_fp16_kernel(
    const __half* __restrict__ A, const __half* __restrict__ B,
    const float* __restrict__ bias, void* __restrict__ OutV,
    const int* __restrict__ rows_list, const int* __restrict__ cnt,
    int N, int K) {
    const int e = blockIdx.z;
    const int m0 = blockIdx.y * BMM;
    const int cn = cnt[e];
    if (m0 >= cn) return;
    const int n0 = blockIdx.x * BNN;

    extern __shared__ __align__(16) __half sh[];
    const uint32_t sbase = smem_u32(sh);

    const int tid = threadIdx.x;
    const int lane = tid & 31;
    const int warp = tid >> 5;
    const int g = lane >> 2;
    const int t = lane & 3;
    const int wm = warp >> 1;  // 0..1
    const int wn = warp & 1;   // 0..1

    const __half* Ae = A + ((size_t)e * TOKENS + m0) * K + (size_t)tid * K;
    const __half* Be = B + ((size_t)e * N + n0) * (size_t)K + (size_t)tid * K;

    float c[4][8][4];
    #pragma unroll
    for (int mi = 0; mi < 4; mi++)
        #pragma unroll
        for (int ni = 0; ni < 8; ni++)
            #pragma unroll
            for (int r = 0; r < 4; r++) c[mi][ni][r] = 0.f;

    const int KT = K / BKH;
    const uint32_t dbase = sbase + tid * 96;

    // prologue: stages 0..2
    #pragma unroll
    for (int kt = 0; kt < NS - 1; kt++) {
        uint32_t ab = dbase + kt * STAGE_BYTES;
        #pragma unroll
        for (int q = 0; q < 4; q++) {
            cpa16(ab + q * 16, Ae + kt * 32 + q * 8);
            cpa16(ab + 12288 + q * 16, Be + kt * 32 + q * 8);
        }
        asm volatile("cp.async.commit_group;" ::: "memory");
    }

    for (int kt = 0; kt < KT; kt++) {
        asm volatile("cp.async.wait_group 2;" ::: "memory");
        __syncthreads();
        int kn = kt + NS - 1;
        if (kn < KT) {
            uint32_t ab = dbase + (kn & 3) * STAGE_BYTES;
            #pragma unroll
            for (int q = 0; q < 4; q++) {
                cpa16(ab + q * 16, Ae + kn * 32 + q * 8);
                cpa16(ab + 12288 + q * 16, Be + kn * 32 + q * 8);
            }
        }
        asm volatile("cp.async.commit_group;" ::: "memory");

        const __half* As = sh + (size_t)(kt & 3) * STAGE_HALVES;
        const __half* Bs = As + BMM * STRH;
        #pragma unroll
        for (int ks = 0; ks < 2; ks++) {
            uint2 af[4][2];
            #pragma unroll
            for (int mi = 0; mi < 4; mi++) {
                int r = wm * 64 + mi * 16 + g;
                af[mi][0] = *(const uint2*)(As + r * STRH + ks * 16 + 4 * t);
                af[mi][1] = *(const uint2*)(As + (r + 8) * STRH + ks * 16 + 4 * t);
            }
            #pragma unroll
            for (int ni = 0; ni < 8; ni++) {
                int n = wn * 64 + ni * 8 + g;
                uint2 bv = *(const uint2*)(Bs + n * STRH + ks * 16 + 4 * t);
                #pragma unroll
                for (int mi = 0; mi < 4; mi++)
                    mma_f16(c[mi][ni], af[mi][0].x, af[mi][1].x,
                            af[mi][0].y, af[mi][1].y, bv.x, bv.y);
            }
        }
    }

    // epilogue
    #pragma unroll
    for (int mi = 0; mi < 4; mi++) {
        int p0 = m0 + wm * 64 + mi * 16 + g;
        int p1 = p0 + 8;
        bool v0 = p0 < cn, v1 = p1 < cn;
        int s0 = 0, s1 = 0;
        if (!GELU_PERM) {
            s0 = v0 ? rows_list[e * TOKENS + p0] : 0;
            s1 = v1 ? rows_list[e * TOKENS + p1] : 0;
        }
        #pragma unroll
        for (int ni = 0; ni < 8; ni++) {
            int C8 = n0 + wn * 64 + ni * 8;
            int col = C8 + 2 * t;
            float2 bv = *(const float2*)(bias + (size_t)e * N + col);
            float x0 = c[mi][ni][0] + bv.x;
            float x1 = c[mi][ni][1] + bv.y;
            float x2 = c[mi][ni][2] + bv.x;
            float x3 = c[mi][ni][3] + bv.y;
            if (GELU_PERM) {
                __half* H = (__half*)OutV;
                int idx = (C8 & ~15) + 4 * t + 2 * (ni & 1);
                if (v0) {
                    __half2 h = __floats2half2_rn(gelu_exact(x0), gelu_exact(x1));
                    *(__half2*)(H + ((size_t)e * TOKENS + p0) * N + idx) = h;
                }
                if (v1) {
                    __half2 h = __floats2half2_rn(gelu_exact(x2), gelu_exact(x3));
                    *(__half2*)(H + ((size_t)e * TOKENS + p1) * N + idx) = h;
                }
            } else {
                float* Y = (float*)OutV;
                if (v0) *(float2*)(Y + (size_t)s0 * N + col) = make_float2(x0, x1);
                if (v1) *(float2*)(Y + (size_t)s1 * N + col) = make_float2(x2, x3);
            }
        }
    }
}

// ---------------- combine: out[t] = g0*Y[2t] + g1*Y[2t+1] ----------------
__global__ void __launch_bounds__(256) combine_kernel(
    const float* __restrict__ Y, const float* __restrict__ gates,
    float* __restrict__ out) {
    int idx = blockIdx.x * blockDim.x + threadIdx.x;
    const int JW = OUTD / 4;  // 448
    if (idx >= TOKENS * JW) return;
    int t = idx / JW;
    int j = idx - t * JW;
    float g0 = gates[2 * t];
    float g1 = gates[2 * t + 1];
    float4 y0 = ((const float4*)(Y + (size_t)(2 * t) * OUTD))[j];
    float4 y1 = ((const float4*)(Y + (size_t)(2 * t + 1) * OUTD))[j];
    float4 o;
    o.x = g0 * y0.x + g1 * y1.x;
    o.y = g0 * y0.y + g1 * y1.y;
    o.z = g0 * y0.z + g1 * y1.z;
    o.w = g0 * y0.w + g1 * y1.w;
    ((float4*)(out + (size_t)t * OUTD))[j] = o;
}

// ---------------- launch ----------------
extern "C" void kernel_launch(void* const* d_in, const int* in_sizes, int n_in,
                              void* d_out, int out_size) {
    const float* hs = (const float*)d_in[0];
    const float* rw = (const float*)d_in[1];
    const float* rb = (const float*)d_in[2];
    const float* w1 = (const float*)d_in[3];
    const float* b1 = (const float*)d_in[4];
    const float* w2 = (const float*)d_in[5];
    const float* b2 = (const float*)d_in[6];
    float* out = (float*)d_out;

    __half *A, *W1P, *W2P, *H;
    float *Y, *gates;
    int *cnt, *rows;
    cudaGetSymbolAddress((void**)&A, g_A);
    cudaGetSymbolAddress((void**)&W1P, g_W1P);
    cudaGetSymbolAddress((void**)&W2P, g_W2P);
    cudaGetSymbolAddress((void**)&H, g_H);
    cudaGetSymbolAddress((void**)&Y, g_Y);
    cudaGetSymbolAddress((void**)&gates, g_gates);
    cudaGetSymbolAddress((void**)&cnt, g_cnt);
    cudaGetSymbolAddress((void**)&rows, g_rows);

    cudaFuncSetAttribute((const void*)gemm_fp16_kernel<true>,
                         cudaFuncAttributeMaxDynamicSharedMemorySize, SMEM_DYN);
    cudaFuncSetAttribute((const void*)gemm_fp16_kernel<false>,
                         cudaFuncAttributeMaxDynamicSharedMemorySize, SMEM_DYN);

    init_cnt_kernel<<<1, 32>>>(cnt);
    router_kernel<<<TOKENS / 8, 256>>>(hs, rw, rb, cnt, rows, gates);
    gather_kernel<<<dim3(TOKENS, NEXP), 128>>>(hs, rows, cnt, A);
    wtrans_kernel<<<dim3(FDIM / 32, HID / 32, NEXP), 256>>>(w1, W1P, HID, FDIM);
    wtrans_kernel<<<dim3(OUTD / 32, FDIM / 32, NEXP), 256>>>(w2, W2P, FDIM, OUTD);

    // GEMM1: A[E][T][HID] x W1P[E][FDIM][HID] -> GELU -> H (fp16, perm)
    gemm_fp16_kernel<true><<<dim3(FDIM / BNN, TOKENS / BMM, NEXP), 128, SMEM_DYN>>>(
        A, W1P, b1, (void*)H, rows, cnt, FDIM, HID);
    // GEMM2: H[E][T][FDIM] x W2P[E][OUTD][FDIM] -> Y (fp32, scattered by slot)
    gemm_fp16_kernel<false><<<dim3(OUTD / BNN, TOKENS / BMM, NEXP), 128, SMEM_DYN>>>(
        H, W2P, b2, (void*)Y, rows, cnt, OUTD, FDIM);

    combine_kernel<<<(TOKENS * (OUTD / 4) + 255) / 256, 256>>>(Y, gates, out);
}

// round 7
// speedup vs baseline: 2.2763x; 1.7647x over previous
#include <cuda_runtime.h>
#include <cuda_fp16.h>
#include <math.h>
#include <stdint.h>

#define TOKENS 4096
#define HID    4096
#define NEXP   4
#define FDIM   8192
#define OUTD   1792

// GEMM tiling: CTA 128x128, BK=32 halves, 8 warps @ 64x32, 4-stage cp.async
#define BMM 128
#define BNN 128
#define ASTRB 80                      // A smem row stride bytes (64B data + 16 pad)
#define BSTRB 272                     // B smem row stride bytes (256B data + 16 pad)
#define A_ST (BMM * ASTRB)            // 10240
#define B_ST (32 * BSTRB)             // 8704
#define STAGE (A_ST + B_ST)           // 18944
#define NS 4
#define SMEM_DYN (NS * STAGE)         // 75776

// ---------------- scratch (device globals) ----------------
__device__ __align__(1024) __half g_hs16[(size_t)TOKENS * HID];          // 33.5MB
__device__ __align__(1024) __half g_W1h[(size_t)NEXP * HID * FDIM];      // 268MB
__device__ __align__(1024) __half g_W2h[(size_t)NEXP * FDIM * OUTD];     // 117MB
__device__ __align__(1024) __half g_H[(size_t)NEXP * TOKENS * FDIM];     // 268MB
__device__ __align__(1024) float  g_Y[(size_t)2 * TOKENS * OUTD];        // 56MB
__device__ __align__(256) float g_gates[2 * TOKENS];
__device__ __align__(256) int   g_rows[NEXP * TOKENS];
__device__ __align__(256) int   g_cnt[NEXP];

// ---------------- helpers ----------------
__device__ __forceinline__ uint32_t smem_u32(const void* p) {
    uint32_t a;
    asm("{ .reg .u64 t; cvta.to.shared.u64 t, %1; cvt.u32.u64 %0, t; }" : "=r"(a) : "l"(p));
    return a;
}
__device__ __forceinline__ void cpa16(uint32_t dst, const void* src) {
    asm volatile("cp.async.cg.shared.global [%0], [%1], 16;" :: "r"(dst), "l"(src));
}
__device__ __forceinline__ float gelu_exact(float x) {
    return 0.5f * x * (1.0f + erff(x * 0.70710678118654752440f));
}
__device__ __forceinline__ uint4 ldsm4(uint32_t a) {
    uint4 r;
    asm volatile("ldmatrix.sync.aligned.m8n8.x4.shared.b16 {%0,%1,%2,%3}, [%4];"
                 : "=r"(r.x), "=r"(r.y), "=r"(r.z), "=r"(r.w) : "r"(a));
    return r;
}
__device__ __forceinline__ uint4 ldsm4t(uint32_t a) {
    uint4 r;
    asm volatile("ldmatrix.sync.aligned.m8n8.x4.trans.shared.b16 {%0,%1,%2,%3}, [%4];"
                 : "=r"(r.x), "=r"(r.y), "=r"(r.z), "=r"(r.w) : "r"(a));
    return r;
}
__device__ __forceinline__ void mma_f16(float c[4],
                                        uint32_t a0, uint32_t a1, uint32_t a2, uint32_t a3,
                                        uint32_t b0, uint32_t b1) {
    asm volatile(
        "mma.sync.aligned.m16n8k16.row.col.f32.f16.f16.f32 "
        "{%0,%1,%2,%3}, {%4,%5,%6,%7}, {%8,%9}, {%0,%1,%2,%3};\n"
        : "+f"(c[0]), "+f"(c[1]), "+f"(c[2]), "+f"(c[3])
        : "r"(a0), "r"(a1), "r"(a2), "r"(a3), "r"(b0), "r"(b1));
}

// ---------------- init ----------------
__global__ void init_cnt_kernel(int* cnt) {
    if (threadIdx.x < NEXP) cnt[threadIdx.x] = 0;
}

// ---------------- router: 1 warp per token ----------------
__global__ void __launch_bounds__(256) router_kernel(
    const float* __restrict__ hs, const float* __restrict__ rw,
    const float* __restrict__ rb, int* __restrict__ cnt,
    int* __restrict__ rows, float* __restrict__ gates) {
    int warp = threadIdx.x >> 5;
    int lane = threadIdx.x & 31;
    int t = blockIdx.x * 8 + warp;
    if (t >= TOKENS) return;

    float a0 = 0.f, a1 = 0.f, a2 = 0.f, a3 = 0.f;
    const float4* x = (const float4*)(hs + (size_t)t * HID);
    const float4* w = (const float4*)rw;
    #pragma unroll 4
    for (int i = lane; i < HID / 4; i += 32) {
        float4 v = x[i];
        float4 w0 = w[4 * i + 0];
        float4 w1 = w[4 * i + 1];
        float4 w2 = w[4 * i + 2];
        float4 w3 = w[4 * i + 3];
        a0 += v.x * w0.x + v.y * w1.x + v.z * w2.x + v.w * w3.x;
        a1 += v.x * w0.y + v.y * w1.y + v.z * w2.y + v.w * w3.y;
        a2 += v.x * w0.z + v.y * w1.z + v.z * w2.z + v.w * w3.z;
        a3 += v.x * w0.w + v.y * w1.w + v.z * w2.w + v.w * w3.w;
    }
    #pragma unroll
    for (int s = 16; s > 0; s >>= 1) {
        a0 += __shfl_xor_sync(0xffffffffu, a0, s);
        a1 += __shfl_xor_sync(0xffffffffu, a1, s);
        a2 += __shfl_xor_sync(0xffffffffu, a2, s);
        a3 += __shfl_xor_sync(0xffffffffu, a3, s);
    }
    if (lane == 0) {
        float l[NEXP] = {a0 + rb[0], a1 + rb[1], a2 + rb[2], a3 + rb[3]};
        int i0 = 0;
        #pragma unroll
        for (int e = 1; e < NEXP; e++)
            if (l[e] > l[i0]) i0 = e;
        int i1 = -1;
        #pragma unroll
        for (int e = 0; e < NEXP; e++) {
            if (e == i0) continue;
            if (i1 < 0 || l[e] > l[i1]) i1 = e;
        }
        float q = expf(l[i1] - l[i0]);  // <= 1
        float g0 = 1.0f / (1.0f + q);
        float g1 = q / (1.0f + q);
        int p0 = atomicAdd(&cnt[i0], 1);
        rows[i0 * TOKENS + p0] = 2 * t;
        int p1 = atomicAdd(&cnt[i1], 1);
        rows[i1 * TOKENS + p1] = 2 * t + 1;
        gates[2 * t] = g0;
        gates[2 * t + 1] = g1;
    }
}

// ---------------- streaming fp32 -> fp16 convert ----------------
__global__ void __launch_bounds__(256) cvt_kernel(
    const float* __restrict__ src, __half* __restrict__ dst, size_t n8) {
    size_t idx = (size_t)blockIdx.x * 256 + threadIdx.x;
    if (idx >= n8) return;
    const float4* s = (const float4*)(src + idx * 8);
    float4 v0 = s[0], v1 = s[1];
    __half h[8];
    h[0] = __float2half_rn(v0.x); h[1] = __float2half_rn(v0.y);
    h[2] = __float2half_rn(v0.z); h[3] = __float2half_rn(v0.w);
    h[4] = __float2half_rn(v1.x); h[5] = __float2half_rn(v1.y);
    h[6] = __float2half_rn(v1.z); h[7] = __float2half_rn(v1.w);
    *(uint4*)(dst + idx * 8) = *(uint4*)h;
}

// ---------------- fp16 tensor-core GEMM, ldmatrix + cp.async ----------------
// A rows staged via per-thread pointers: GATHER -> hs16[rows_list[p]>>1],
// else H[e*TOKENS+p]. B native [E][K][N] fp16.
template <bool GATHER, bool GELU>
__global__ void __launch_bounds__(256, 2) gemm16_kernel(
    const __half* __restrict__ Ab, const __half* __restrict__ Bb,
    const float* __restrict__ bias, void* __restrict__ OutV,
    const int* __restrict__ rows_list, const int* __restrict__ cnt,
    int N, int K) {
    const int e = blockIdx.z;
    const int m0 = blockIdx.y * BMM;
    const int cn = cnt[e];
    if (m0 >= cn) return;
    const int n0 = blockIdx.x * BNN;

    extern __shared__ __align__(16) char sh[];
    const uint32_t sb = smem_u32(sh);

    const int tid = threadIdx.x;
    const int lane = tid & 31;
    const int warp = tid >> 5;
    const int g = lane >> 2;
    const int t = lane & 3;
    const int wm = warp >> 2;  // 0..1 -> m offset 64*wm
    const int wn = warp & 3;   // 0..3 -> n offset 32*wn

    // staging source pointers
    int pc = m0 + (tid >> 1);
    int pcl = pc < cn - 1 ? pc : cn - 1;
    size_t arow = GATHER ? (size_t)(rows_list[e * TOKENS + pcl] >> 1)
                         : (size_t)(e * TOKENS + pcl);
    const __half* aptr = Ab + arow * (size_t)K + (tid & 1) * 16;
    const __half* bptr = Bb + ((size_t)e * K + (tid >> 3)) * N + n0 + (tid & 7) * 16;

    // staging dst offsets
    const uint32_t adst = sb + (tid >> 1) * ASTRB + (tid & 1) * 32;
    const uint32_t bdst = sb + A_ST + (tid >> 3) * BSTRB + (tid & 7) * 32;

    // ldmatrix per-lane offsets
    const uint32_t a_lane = (lane & 15) * ASTRB + (lane >> 4) * 16;
    const uint32_t b_lane = ((lane & 7) + 8 * ((lane >> 3) & 1)) * BSTRB + (lane >> 4) * 16;

    float c[4][4][4];
    #pragma unroll
    for (int mi = 0; mi < 4; mi++)
        #pragma unroll
        for (int ni = 0; ni < 4; ni++)
            #pragma unroll
            for (int r = 0; r < 4; r++) c[mi][ni][r] = 0.f;

    const int KT = K / 32;

    #define ISSUE(kt) do { \
        uint32_t sa = adst + ((kt) & 3) * STAGE; \
        uint32_t sbs = bdst + ((kt) & 3) * STAGE; \
        const __half* as_ = aptr + (size_t)(kt) * 32; \
        const __half* bs_ = bptr + (size_t)(kt) * 32 * N; \
        cpa16(sa, as_); \
        cpa16(sa + 16, as_ + 8); \
        cpa16(sbs, bs_); \
        cpa16(sbs + 16, bs_ + 8); \
    } while (0)

    #pragma unroll
    for (int kt = 0; kt < NS - 1; kt++) {
        ISSUE(kt);
        asm volatile("cp.async.commit_group;" ::: "memory");
    }

    for (int kt = 0; kt < KT; kt++) {
        asm volatile("cp.async.wait_group 2;" ::: "memory");
        __syncthreads();
        if (kt + NS - 1 < KT) ISSUE(kt + NS - 1);
        asm volatile("cp.async.commit_group;" ::: "memory");

        const uint32_t stA = sb + (kt & 3) * STAGE;
        const uint32_t stB = stA + A_ST;
        #pragma unroll
        for (int ks = 0; ks < 2; ks++) {
            uint4 af[4];
            const uint32_t ab = stA + a_lane + ks * 32 + wm * 64 * ASTRB;
            #pragma unroll
            for (int mi = 0; mi < 4; mi++)
                af[mi] = ldsm4(ab + mi * 16 * ASTRB);
            uint4 bf[2];
            const uint32_t bbs = stB + b_lane + ks * 16 * BSTRB + wn * 64;
            #pragma unroll
            for (int nj = 0; nj < 2; nj++)
                bf[nj] = ldsm4t(bbs + nj * 32);
            #pragma unroll
            for (int mi = 0; mi < 4; mi++) {
                #pragma unroll
                for (int nj = 0; nj < 2; nj++) {
                    mma_f16(c[mi][2 * nj], af[mi].x, af[mi].y, af[mi].z, af[mi].w,
                            bf[nj].x, bf[nj].y);
                    mma_f16(c[mi][2 * nj + 1], af[mi].x, af[mi].y, af[mi].z, af[mi].w,
                            bf[nj].z, bf[nj].w);
                }
            }
        }
    }
    #undef ISSUE

    // epilogue
    #pragma unroll
    for (int mi = 0; mi < 4; mi++) {
        int p0 = m0 + wm * 64 + mi * 16 + g;
        int p1 = p0 + 8;
        bool v0 = p0 < cn, v1 = p1 < cn;
        int s0 = 0, s1 = 0;
        if (!GELU) {
            s0 = v0 ? rows_list[e * TOKENS + p0] : 0;
            s1 = v1 ? rows_list[e * TOKENS + p1] : 0;
        }
        #pragma unroll
        for (int ni = 0; ni < 4; ni++) {
            int col = n0 + wn * 32 + ni * 8 + 2 * t;
            float2 bv = *(const float2*)(bias + (size_t)e * N + col);
            float x0 = c[mi][ni][0] + bv.x;
            float x1 = c[mi][ni][1] + bv.y;
            float x2 = c[mi][ni][2] + bv.x;
            float x3 = c[mi][ni][3] + bv.y;
            if (GELU) {
                __half* H = (__half*)OutV;
                if (v0) {
                    __half2 h = __floats2half2_rn(gelu_exact(x0), gelu_exact(x1));
                    *(__half2*)(H + ((size_t)e * TOKENS + p0) * N + col) = h;
                }
                if (v1) {
                    __half2 h = __floats2half2_rn(gelu_exact(x2), gelu_exact(x3));
                    *(__half2*)(H + ((size_t)e * TOKENS + p1) * N + col) = h;
                }
            } else {
                float* Y = (float*)OutV;
                if (v0) *(float2*)(Y + (size_t)s0 * N + col) = make_float2(x0, x1);
                if (v1) *(float2*)(Y + (size_t)s1 * N + col) = make_float2(x2, x3);
            }
        }
    }
}

// ---------------- combine: out[t] = g0*Y[2t] + g1*Y[2t+1] ----------------
__global__ void __launch_bounds__(256) combine_kernel(
    const float* __restrict__ Y, const float* __restrict__ gates,
    float* __restrict__ out) {
    int idx = blockIdx.x * blockDim.x + threadIdx.x;
    const int JW = OUTD / 4;  // 448
    if (idx >= TOKENS * JW) return;
    int t = idx / JW;
    int j = idx - t * JW;
    float g0 = gates[2 * t];
    float g1 = gates[2 * t + 1];
    float4 y0 = ((const float4*)(Y + (size_t)(2 * t) * OUTD))[j];
    float4 y1 = ((const float4*)(Y + (size_t)(2 * t + 1) * OUTD))[j];
    float4 o;
    o.x = g0 * y0.x + g1 * y1.x;
    o.y = g0 * y0.y + g1 * y1.y;
    o.z = g0 * y0.z + g1 * y1.z;
    o.w = g0 * y0.w + g1 * y1.w;
    ((float4*)(out + (size_t)t * OUTD))[j] = o;
}

// ---------------- launch ----------------
extern "C" void kernel_launch(void* const* d_in, const int* in_sizes, int n_in,
                              void* d_out, int out_size) {
    const float* hs = (const float*)d_in[0];
    const float* rw = (const float*)d_in[1];
    const float* rb = (const float*)d_in[2];
    const float* w1 = (const float*)d_in[3];
    const float* b1 = (const float*)d_in[4];
    const float* w2 = (const float*)d_in[5];
    const float* b2 = (const float*)d_in[6];
    float* out = (float*)d_out;

    __half *hs16, *W1h, *W2h, *H;
    float *Y, *gates;
    int *cnt, *rows;
    cudaGetSymbolAddress((void**)&hs16, g_hs16);
    cudaGetSymbolAddress((void**)&W1h, g_W1h);
    cudaGetSymbolAddress((void**)&W2h, g_W2h);
    cudaGetSymbolAddress((void**)&H, g_H);
    cudaGetSymbolAddress((void**)&Y, g_Y);
    cudaGetSymbolAddress((void**)&gates, g_gates);
    cudaGetSymbolAddress((void**)&cnt, g_cnt);
    cudaGetSymbolAddress((void**)&rows, g_rows);

    cudaFuncSetAttribute((const void*)gemm16_kernel<true, true>,
                         cudaFuncAttributeMaxDynamicSharedMemorySize, SMEM_DYN);
    cudaFuncSetAttribute((const void*)gemm16_kernel<false, false>,
                         cudaFuncAttributeMaxDynamicSharedMemorySize, SMEM_DYN);

    init_cnt_kernel<<<1, 32>>>(cnt);
    router_kernel<<<TOKENS / 8, 256>>>(hs, rw, rb, cnt, rows, gates);

    size_t n_hs = (size_t)TOKENS * HID / 8;
    size_t n_w1 = (size_t)NEXP * HID * FDIM / 8;
    size_t n_w2 = (size_t)NEXP * FDIM * OUTD / 8;
    cvt_kernel<<<(unsigned)((n_hs + 255) / 256), 256>>>(hs, hs16, n_hs);
    cvt_kernel<<<(unsigned)((n_w1 + 255) / 256), 256>>>(w1, W1h, n_w1);
    cvt_kernel<<<(unsigned)((n_w2 + 255) / 256), 256>>>(w2, W2h, n_w2);

    // GEMM1: hs16 (gathered rows) x W1h[E][HID][FDIM] -> GELU -> H fp16
    gemm16_kernel<true, true><<<dim3(FDIM / BNN, TOKENS / BMM, NEXP), 256, SMEM_DYN>>>(
        hs16, W1h, b1, (void*)H, rows, cnt, FDIM, HID);
    // GEMM2: H x W2h[E][FDIM][OUTD] -> Y fp32 (scattered by slot)
    gemm16_kernel<false, false><<<dim3(OUTD / BNN, TOKENS / BMM, NEXP), 256, SMEM_DYN>>>(
        H, W2h, b2, (void*)Y, rows, cnt, OUTD, FDIM);

    combine_kernel<<<(TOKENS * (OUTD / 4) + 255) / 256, 256>>>(Y, gates, out);
}